// round 16
// baseline (speedup 1.0000x reference)
#include <cuda_runtime.h>
#include <math.h>

// Problem dims
#define BATCH 512
#define TT    512
#define DD    128
#define HH    64

#define GE 256      // encoder gates 4H
#define KE 192      // encoder K = D + H
#define GD 512      // decoder gates 4D
#define KD 128      // decoder K = D

typedef unsigned long long u64t;

// ---------------- device scratch ----------------
__device__ __align__(16) float g_WeFrag[2 * 8 * 24 * 128];  // 49152: encoder Whh+Wih tf32 mma fragments
__device__ __align__(16) float g_WdFrag[2 * 16 * 16 * 128]; // 65536: decoder Whh tf32 mma fragments
__device__ __align__(16) float g_Wihd2[2 * HH * 256];       // 32768: decoder input proj [role][k][lrow]
__device__ __align__(16) float g_henc  [BATCH * HH];

// ---------------- helpers ----------------
__device__ __forceinline__ float tanh_ap(float x) {
    asm("tanh.approx.f32 %0, %0;" : "+f"(x)); return x;
}
__device__ __forceinline__ float sig_ap(float x) {
    return fmaf(tanh_ap(0.5f * x), 0.5f, 0.5f);
}
__device__ __forceinline__ unsigned tf32r(float f) {
    unsigned u; asm("cvt.rna.tf32.f32 %0, %1;" : "=r"(u) : "f"(f)); return u;
}
__device__ __forceinline__ float tf32f(float f) { return __uint_as_float(tf32r(f)); }
__device__ __forceinline__ void mma_tf32(float d[4],
                                         unsigned a0, unsigned a1, unsigned a2, unsigned a3,
                                         unsigned b0, unsigned b1) {
    asm volatile(
        "mma.sync.aligned.m16n8k8.row.col.f32.tf32.tf32.f32 "
        "{%0,%1,%2,%3}, {%4,%5,%6,%7}, {%8,%9}, {%0,%1,%2,%3};"
        : "+f"(d[0]), "+f"(d[1]), "+f"(d[2]), "+f"(d[3])
        : "r"(a0), "r"(a1), "r"(a2), "r"(a3), "r"(b0), "r"(b1));
}
#define CLUSTER_SYNC() do { \
    asm volatile("barrier.cluster.arrive.aligned;" ::: "memory"); \
    asm volatile("barrier.cluster.wait.aligned;" ::: "memory"); \
} while (0)
// split cluster barrier: arrive is non-blocking (release), wait blocks (acquire).
#define CLUSTER_ARRIVE() asm volatile("barrier.cluster.arrive.aligned;" ::: "memory")
#define CLUSTER_WAIT()   asm volatile("barrier.cluster.wait.aligned;" ::: "memory")

// ---------------- prep: build tf32 mma fragments (one-time, tiny) ----------------
__global__ void prep_kernel(const float* __restrict__ Wih_e,
                            const float* __restrict__ Whh_e,
                            const float* __restrict__ Whh_d,
                            const float* __restrict__ Wih_d) {
    int idx = blockIdx.x * 256 + threadIdx.x;            // 0 .. 147455
    if (idx < 49152) {                                   // encoder fragments
        int wblk = idx / 3072;                           // role*8 + w
        int rem  = idx - wblk * 3072;
        int kt = rem >> 7;                               // 0..23
        int r2 = rem & 127;
        int l = r2 >> 2, c = r2 & 3;
        int gr = l >> 2, gc = l & 3;
        int row = (wblk >> 3) * 128 + (wblk & 7) * 16 + gr + (c & 1) * 8;   // 0..255
        int k   = kt * 8 + gc + ((c >> 1) & 1) * 4;                          // 0..191
        float v = (k < DD) ? Wih_e[row * DD + k] : Whh_e[row * HH + (k - DD)];
        g_WeFrag[idx] = __uint_as_float(tf32r(v));
        return;
    }
    int f = idx - 49152;
    if (f < 65536) {                                     // decoder fragments (validated)
        int rw = f >> 11;
        int role = rw >> 4, w = rw & 15;
        int rem = f & 2047;
        int i4 = rem >> 7;
        int r2 = rem & 127;
        int l = r2 >> 2, c = r2 & 3;
        int gr = l >> 2, gc = l & 3;
        int lrow = w * 16 + gr + (c & 1) * 8;
        int k = i4 * 8 + gc + ((c >> 1) & 1) * 4;
        int gate = lrow >> 6, j = lrow & 63;
        int grow = gate * 128 + role * 64 + j;
        g_WdFrag[f] = __uint_as_float(tf32r(Whh_d[grow * 128 + k]));
        return;
    }
    int f2 = f - 65536;
    if (f2 < 32768) {                                    // decoder input proj [role][k][lrow]
        int rolek = f2 >> 8, lr = f2 & 255;
        int role = rolek >> 6, k = rolek & 63;
        int gate = lr >> 6, j = lr & 63;
        int grow = gate * 128 + role * 64 + j;
        g_Wihd2[f2] = Wih_d[grow * 64 + k];
    }
}

// ---------------- encoder: 2-CTA cluster, pipelined tf32 mma ----------------
// 64 clusters x 2 CTAs x 8 batches; 256 threads/CTA; CTA role r owns gate rows [r*128, r*128+128).
// SMEM floats: xs[2][8][132] 2112 | hs[2][8][72] 1152 | gsm[2][256][9] 4608
#define EXS 0
#define EHS 2112
#define EGS 3264
#define ENC_SMEM_F (EGS + 4608)
#define ENC_SMEM_BYTES (ENC_SMEM_F * 4)

__global__ __launch_bounds__(256, 1) __cluster_dims__(2, 1, 1)
void enc_kernel(const float* __restrict__ x, const float* __restrict__ b_e) {
    extern __shared__ float sm[];
    float* xs  = sm + EXS;     // [2][8 b][132]      double-buffered x_t (tf32-rounded)
    float* hs  = sm + EHS;     // [2][8 b][72]       double-buffered hidden
    float* gsm = sm + EGS;     // [2][256 row][9 b]  double-buffered gates

    const int tid = threadIdx.x;
    const int w = tid >> 5, l = tid & 31;
    const int gr = l >> 2, gc = l & 3;
    unsigned rank;
    asm("mov.u32 %0, %%cluster_ctarank;" : "=r"(rank));
    const int bb = (blockIdx.x >> 1) * 8;

    // A fragments: 24 k-tiles x float4
    float4 af[24];
    {
        const float4* Asrc = (const float4*)g_WeFrag + ((int)rank * 8 + w) * 768;
        #pragma unroll
        for (int kt = 0; kt < 24; ++kt) af[kt] = Asrc[kt * 32 + l];
    }
    const int row0 = (int)rank * 128 + w * 16 + gr;
    const float bsr0 = b_e[row0], bsr1 = b_e[row0 + 8];

    for (int i = tid; i < 1152; i += 256) hs[i] = 0.0f;

    // stage x_0 into xs[0]; load x_1 into regs
    const int xb = tid >> 5, xk = (tid & 31) * 4;
    {
        float4 v = *(const float4*)&x[(size_t)(bb + xb) * TT * DD + xk];
        float* d = &xs[xb * 132 + xk];
        d[0] = tf32f(v.x); d[1] = tf32f(v.y); d[2] = tf32f(v.z); d[3] = tf32f(v.w);
    }
    float4 x1 = *(const float4*)&x[(size_t)(bb + xb) * TT * DD + (size_t)1 * DD + xk];
    __syncthreads();
    CLUSTER_SYNC();            // init state visible cluster-wide

    unsigned gU = (unsigned)__cvta_generic_to_shared(gsm);
    unsigned remG;
    asm("mapa.shared::cluster.u32 %0, %1, %2;" : "=r"(remG) : "r"(gU), "r"(rank ^ 1u));

    // ---- prologue: gates_0 = bias + x_0 part (h_{-1}=0) ----
    {
        float dd[4] = {bsr0, bsr0, bsr1, bsr1};
        float ee[4] = {0.f, 0.f, 0.f, 0.f};
        #pragma unroll
        for (int kt = 0; kt < 16; ++kt) {
            float b0 = xs[gr * 132 + kt * 8 + gc];
            float b1 = xs[gr * 132 + kt * 8 + gc + 4];
            mma_tf32((kt & 1) ? ee : dd,
                     __float_as_uint(af[kt].x), __float_as_uint(af[kt].y),
                     __float_as_uint(af[kt].z), __float_as_uint(af[kt].w),
                     __float_as_uint(b0), __float_as_uint(b1));
        }
        float g0 = dd[0] + ee[0], g1 = dd[1] + ee[1];
        float g2 = dd[2] + ee[2], g3 = dd[3] + ee[3];
        unsigned o0 = (unsigned)((row0 * 9 + 2 * gc) * 4);
        unsigned o1 = (unsigned)(((row0 + 8) * 9 + 2 * gc) * 4);
        gsm[row0 * 9 + 2 * gc]           = g0;
        gsm[row0 * 9 + 2 * gc + 1]       = g1;
        gsm[(row0 + 8) * 9 + 2 * gc]     = g2;
        gsm[(row0 + 8) * 9 + 2 * gc + 1] = g3;
        asm volatile("st.shared::cluster.f32 [%0], %1;" :: "r"(remG + o0),     "f"(g0) : "memory");
        asm volatile("st.shared::cluster.f32 [%0], %1;" :: "r"(remG + o0 + 4), "f"(g1) : "memory");
        asm volatile("st.shared::cluster.f32 [%0], %1;" :: "r"(remG + o1),     "f"(g2) : "memory");
        asm volatile("st.shared::cluster.f32 [%0], %1;" :: "r"(remG + o1 + 4), "f"(g3) : "memory");
    }
    CLUSTER_ARRIVE();
    // commit x_1 into xs[1]; prefetch x_2
    {
        float* d = &xs[1056 + xb * 132 + xk];
        d[0] = tf32f(x1.x); d[1] = tf32f(x1.y); d[2] = tf32f(x1.z); d[3] = tf32f(x1.w);
    }
    float4 xn = *(const float4*)&x[(size_t)(bb + xb) * TT * DD + (size_t)2 * DD + xk];
    __syncthreads();
    // accX for t=1 (bias + x_1 part), overlaps the cluster wait below
    float aX[4] = {bsr0, bsr0, bsr1, bsr1};
    float eX[4] = {0.f, 0.f, 0.f, 0.f};
    #pragma unroll
    for (int kt = 0; kt < 16; ++kt) {
        float b0 = xs[1056 + gr * 132 + kt * 8 + gc];
        float b1 = xs[1056 + gr * 132 + kt * 8 + gc + 4];
        mma_tf32((kt & 1) ? eX : aX,
                 __float_as_uint(af[kt].x), __float_as_uint(af[kt].y),
                 __float_as_uint(af[kt].z), __float_as_uint(af[kt].w),
                 __float_as_uint(b0), __float_as_uint(b1));
    }
    CLUSTER_WAIT();            // gates_0 peer half arrived

    const int ej = tid & 63, eb = tid >> 6;
    float c0 = 0.0f, c1 = 0.0f, h0v = 0.0f, h1v = 0.0f;

    for (int t = 0; t < TT - 1; ++t) {
        const int gb  = (t & 1) * 2304;        // gates_t buffer
        const int hb  = (t & 1) * 576;         // h_t write buffer
        const int xbf = (t & 1) * 1056;        // xs[(t+2)&1]

        // (1) elementwise on gates_t -> h_t
        {
            const float* g = gsm + gb;
            float gi = g[(ej)       * 9 + eb];
            float gf = g[(64 + ej)  * 9 + eb];
            float gg = g[(128 + ej) * 9 + eb];
            float go = g[(192 + ej) * 9 + eb];
            float i_ = sig_ap(gi), f_ = sig_ap(gf), gv = tanh_ap(gg), o_ = sig_ap(go);
            c0 = f_ * c0 + i_ * gv;
            h0v = o_ * tanh_ap(c0);
            hs[hb + eb * 72 + ej] = tf32f(h0v);

            gi = g[(ej)       * 9 + eb + 4];
            gf = g[(64 + ej)  * 9 + eb + 4];
            gg = g[(128 + ej) * 9 + eb + 4];
            go = g[(192 + ej) * 9 + eb + 4];
            i_ = sig_ap(gi); f_ = sig_ap(gf); gv = tanh_ap(gg); o_ = sig_ap(go);
            c1 = f_ * c1 + i_ * gv;
            h1v = o_ * tanh_ap(c1);
            hs[hb + (eb + 4) * 72 + ej] = tf32f(h1v);
        }
        // (2) h_t visible locally
        __syncthreads();
        // (3) mma_h: add h_t part to accX -> gates_{t+1} (short 8-mma chain)
        #pragma unroll
        for (int i = 0; i < 8; ++i) {
            int kk = i * 8;
            float b0 = hs[hb + gr * 72 + kk + gc];
            float b1 = hs[hb + gr * 72 + kk + gc + 4];
            mma_tf32((i & 1) ? eX : aX,
                     __float_as_uint(af[16 + i].x), __float_as_uint(af[16 + i].y),
                     __float_as_uint(af[16 + i].z), __float_as_uint(af[16 + i].w),
                     __float_as_uint(b0), __float_as_uint(b1));
        }
        float g0 = aX[0] + eX[0], g1 = aX[1] + eX[1];
        float g2 = aX[2] + eX[2], g3 = aX[3] + eX[3];
        // (4) store gates_{t+1} local + peer, arrive
        {
            const int gb2 = ((t + 1) & 1) * 2304;
            unsigned o0 = (unsigned)((gb2 + row0 * 9 + 2 * gc) * 4);
            unsigned o1 = (unsigned)((gb2 + (row0 + 8) * 9 + 2 * gc) * 4);
            gsm[gb2 + row0 * 9 + 2 * gc]           = g0;
            gsm[gb2 + row0 * 9 + 2 * gc + 1]       = g1;
            gsm[gb2 + (row0 + 8) * 9 + 2 * gc]     = g2;
            gsm[gb2 + (row0 + 8) * 9 + 2 * gc + 1] = g3;
            asm volatile("st.shared::cluster.f32 [%0], %1;" :: "r"(remG + o0),     "f"(g0) : "memory");
            asm volatile("st.shared::cluster.f32 [%0], %1;" :: "r"(remG + o0 + 4), "f"(g1) : "memory");
            asm volatile("st.shared::cluster.f32 [%0], %1;" :: "r"(remG + o1),     "f"(g2) : "memory");
            asm volatile("st.shared::cluster.f32 [%0], %1;" :: "r"(remG + o1 + 4), "f"(g3) : "memory");
        }
        CLUSTER_ARRIVE();
        // (5) commit x_{t+2}; prefetch x_{t+3}
        {
            float* d = &xs[xbf + xb * 132 + xk];
            d[0] = tf32f(xn.x); d[1] = tf32f(xn.y); d[2] = tf32f(xn.z); d[3] = tf32f(xn.w);
        }
        xn = make_float4(0.f, 0.f, 0.f, 0.f);
        if (t + 3 < TT)
            xn = *(const float4*)&x[(size_t)(bb + xb) * TT * DD + (size_t)(t + 3) * DD + xk];
        // (6) x_{t+2} visible + local gates stores visible
        __syncthreads();
        // (7) accX for t+2: 16 mma, overlaps the cluster wait
        aX[0] = bsr0; aX[1] = bsr0; aX[2] = bsr1; aX[3] = bsr1;
        eX[0] = 0.f; eX[1] = 0.f; eX[2] = 0.f; eX[3] = 0.f;
        #pragma unroll
        for (int kt = 0; kt < 16; ++kt) {
            float b0 = xs[xbf + gr * 132 + kt * 8 + gc];
            float b1 = xs[xbf + gr * 132 + kt * 8 + gc + 4];
            mma_tf32((kt & 1) ? eX : aX,
                     __float_as_uint(af[kt].x), __float_as_uint(af[kt].y),
                     __float_as_uint(af[kt].z), __float_as_uint(af[kt].w),
                     __float_as_uint(b0), __float_as_uint(b1));
        }
        // (8) peer gates_{t+1} arrived
        CLUSTER_WAIT();
    }
    // tail: t = TT-1 elementwise only
    {
        const float* g = gsm + ((TT - 1) & 1) * 2304;
        float gi = g[(ej)       * 9 + eb];
        float gf = g[(64 + ej)  * 9 + eb];
        float gg = g[(128 + ej) * 9 + eb];
        float go = g[(192 + ej) * 9 + eb];
        float i_ = sig_ap(gi), f_ = sig_ap(gf), gv = tanh_ap(gg), o_ = sig_ap(go);
        c0 = f_ * c0 + i_ * gv;
        h0v = o_ * tanh_ap(c0);

        gi = g[(ej)       * 9 + eb + 4];
        gf = g[(64 + ej)  * 9 + eb + 4];
        gg = g[(128 + ej) * 9 + eb + 4];
        go = g[(192 + ej) * 9 + eb + 4];
        i_ = sig_ap(gi); f_ = sig_ap(gf); gv = tanh_ap(gg); o_ = sig_ap(go);
        c1 = f_ * c1 + i_ * gv;
        h1v = o_ * tanh_ap(c1);
    }
    g_henc[(bb + eb) * HH + ej]     = h0v;
    g_henc[(bb + eb + 4) * HH + ej] = h1v;
    CLUSTER_SYNC();
}

// ---------------- decoder: cluster mma, local-k-tiles overlap the wait ----------------
// SMEM floats: hsm 2048 | xp 2048 | gsm 2560
#define DEC_SMEM_F 6656
#define DEC_SMEM_BYTES (DEC_SMEM_F * 4)

__global__ __launch_bounds__(512, 1) __cluster_dims__(2, 1, 1)
void dec_kernel(const float* __restrict__ b_d, float* __restrict__ out) {
    extern __shared__ float sm[];
    float* hsm = sm;              // [2][128 k][8 b]
    float* xp  = sm + 2048;       // [256 lrow][8 b]
    float* gsm = sm + 4096;       // [256 lrow][10]
    float* hesm = gsm;            // reuse for h_enc staging

    const int tid = threadIdx.x;
    const int w = tid >> 5, l = tid & 31;
    unsigned rank;
    asm("mov.u32 %0, %%cluster_ctarank;" : "=r"(rank));
    const int bb   = (blockIdx.x >> 1) * 8;
    const int koff = (int)rank * 64;

    float4 af[16];
    {
        const float4* Asrc = (const float4*)g_WdFrag + ((int)rank * 16 + w) * 512;
        #pragma unroll
        for (int i4 = 0; i4 < 16; ++i4) af[i4] = Asrc[i4 * 32 + l];
    }

    hsm[tid] = 0.0f; hsm[512 + tid] = 0.0f;
    hsm[1024 + tid] = 0.0f; hsm[1536 + tid] = 0.0f;
    hesm[tid] = g_henc[bb * 64 + tid];
    __syncthreads();

    {
        int lr = tid >> 1, b4 = (tid & 1) * 4;
        int gate = lr >> 6, j = lr & 63;
        int grow = gate * 128 + koff + j;
        float a0 = b_d[grow], a1 = a0, a2 = a0, a3 = a0;
        #pragma unroll 4
        for (int k = 0; k < HH; ++k) {
            float ww = g_Wihd2[((int)rank * 64 + k) * 256 + lr];
            a0 = fmaf(ww, hesm[(b4 + 0) * 64 + k], a0);
            a1 = fmaf(ww, hesm[(b4 + 1) * 64 + k], a1);
            a2 = fmaf(ww, hesm[(b4 + 2) * 64 + k], a2);
            a3 = fmaf(ww, hesm[(b4 + 3) * 64 + k], a3);
        }
        *(float4*)&xp[lr * 8 + b4] = make_float4(a0, a1, a2, a3);
    }
    __syncthreads();
    CLUSTER_ARRIVE();             // pairs with the wait inside iter 0

    const int gr = l >> 2, gc = l & 3;
    const int wbase = w * 16;
    const int ej = tid & 63, ebb = tid >> 6;
    float creg = 0.0f;

    unsigned hU = (unsigned)__cvta_generic_to_shared(hsm);
    unsigned remBase;
    asm("mapa.shared::cluster.u32 %0, %1, %2;" : "=r"(remBase) : "r"(hU), "r"(rank ^ 1u));
    const unsigned myoff = (unsigned)(((koff + ej) * 8 + ebb) * 4);
    const int lbase = (int)rank * 8;          // my h-half k-tiles
    const int pbase = ((int)rank ^ 1) * 8;    // peer h-half k-tiles

    for (int t = 0; t < TT; ++t) {
        const float* hr = hsm + (((t & 1) ^ 1) << 10);
        const int wb = (t & 1) << 10;

        float2 x01 = *(const float2*)&xp[(wbase + gr) * 8 + 2 * gc];
        float2 x23 = *(const float2*)&xp[(wbase + gr + 8) * 8 + 2 * gc];
        float dd[4] = {x01.x, x01.y, x23.x, x23.y};
        float ee[4] = {0.f, 0.f, 0.f, 0.f};

        // (1) LOCAL k-tiles first — my own h half, no peer dependency
        #pragma unroll
        for (int i = 0; i < 8; ++i) {
            int kt = lbase + i;
            float b0 = hr[(kt * 8 + gc) * 8 + gr];
            float b1 = hr[(kt * 8 + gc + 4) * 8 + gr];
            mma_tf32((i & 1) ? ee : dd,
                     __float_as_uint(af[kt].x), __float_as_uint(af[kt].y),
                     __float_as_uint(af[kt].z), __float_as_uint(af[kt].w),
                     __float_as_uint(b0), __float_as_uint(b1));
        }
        // (2) peer h_{t-1} arrived (overlapped with the 8 MMAs above)
        CLUSTER_WAIT();
        // (3) PEER k-tiles
        #pragma unroll
        for (int i = 0; i < 8; ++i) {
            int kt = pbase + i;
            float b0 = hr[(kt * 8 + gc) * 8 + gr];
            float b1 = hr[(kt * 8 + gc + 4) * 8 + gr];
            mma_tf32((i & 1) ? ee : dd,
                     __float_as_uint(af[kt].x), __float_as_uint(af[kt].y),
                     __float_as_uint(af[kt].z), __float_as_uint(af[kt].w),
                     __float_as_uint(b0), __float_as_uint(b1));
        }
        *(float2*)&gsm[(wbase + gr) * 10 + 2 * gc]     = make_float2(dd[0] + ee[0], dd[1] + ee[1]);
        *(float2*)&gsm[(wbase + gr + 8) * 10 + 2 * gc] = make_float2(dd[2] + ee[2], dd[3] + ee[3]);
        __syncthreads();

        // (4) elementwise -> h_t, out, h exchange
        float gi = gsm[(ej)       * 10 + ebb];
        float gf = gsm[(64 + ej)  * 10 + ebb];
        float gg = gsm[(128 + ej) * 10 + ebb];
        float go = gsm[(192 + ej) * 10 + ebb];
        float i_ = sig_ap(gi), f_ = sig_ap(gf), g_ = tanh_ap(gg), o_ = sig_ap(go);
        creg = f_ * creg + i_ * g_;
        float h_ = o_ * tanh_ap(creg);
        out[((size_t)(bb + ebb) * TT + t) * DD + koff + ej] = h_;

        float hrd = __uint_as_float(tf32r(h_));
        hsm[wb + (koff + ej) * 8 + ebb] = hrd;
        asm volatile("st.shared::cluster.f32 [%0], %1;"
                     :: "r"(remBase + (unsigned)(wb * 4) + myoff), "f"(hrd) : "memory");
        if (t + 1 < TT) CLUSTER_ARRIVE();   // release: orders my DSMEM h store
        __syncthreads();                    // local h_t visible for next iter's local MMAs
    }
    CLUSTER_SYNC();
}

// ---------------- launch ----------------
extern "C" void kernel_launch(void* const* d_in, const int* in_sizes, int n_in,
                              void* d_out, int out_size) {
    const float* x     = (const float*)d_in[0];
    const float* Wih_e = (const float*)d_in[1];
    const float* Whh_e = (const float*)d_in[2];
    const float* b_e   = (const float*)d_in[3];
    const float* Wih_d = (const float*)d_in[4];
    const float* Whh_d = (const float*)d_in[5];
    const float* b_d   = (const float*)d_in[6];
    float* out = (float*)d_out;

    cudaFuncSetAttribute(enc_kernel, cudaFuncAttributeMaxDynamicSharedMemorySize, ENC_SMEM_BYTES);
    cudaFuncSetAttribute(dec_kernel, cudaFuncAttributeMaxDynamicSharedMemorySize, DEC_SMEM_BYTES);

    prep_kernel<<<576, 256>>>(Wih_e, Whh_e, Whh_d, Wih_d);
    enc_kernel<<<BATCH / 8 * 2, 256, ENC_SMEM_BYTES>>>(x, b_e);   // 128 CTAs = 64 clusters
    dec_kernel<<<BATCH / 8 * 2, 512, DEC_SMEM_BYTES>>>(b_d, out); // 128 CTAs = 64 clusters
}